// round 3
// baseline (speedup 1.0000x reference)
#include <cuda_runtime.h>
#include <math.h>

#define NN    50000
#define EE    800000
#define HEADS 4
#define HID   64
#define OUTC  40

// ---------------- scratch (static device globals; no allocations) ----------
__device__ float g_h1  [(size_t)NN * 256];   // layer-1 linear output [N, H*HID]
__device__ float g_out1[(size_t)NN * 256];   // layer-1 GAT output after ELU
__device__ float g_h2  [(size_t)NN * OUTC];  // layer-2 linear output
__device__ float g_alS1[NN * HEADS];
__device__ float g_alD1[NN * HEADS];
__device__ float g_alS2[NN];
__device__ float g_alD2[NN];
__device__ int   g_deg   [NN];
__device__ int   g_rowptr[NN + 1];
__device__ int   g_cursor[NN];
__device__ int   g_csrsrc[EE + NN];

// ---------------- CSR build ------------------------------------------------
__global__ void zero_deg_kernel(int n) {
    int i = blockIdx.x * blockDim.x + threadIdx.x;
    if (i < n) g_deg[i] = 0;
}

__global__ void deg_kernel(const int* __restrict__ dstE, int E, int Etot) {
    int i = blockIdx.x * blockDim.x + threadIdx.x;
    if (i < Etot) {
        int d = (i < E) ? dstE[i] : (i - E);   // self-loop for i >= E
        atomicAdd(&g_deg[d], 1);
    }
}

// single-block exclusive scan over g_deg -> g_rowptr, g_cursor
__global__ void scan_kernel(int n) {
    __shared__ int sums[1024];
    int tid = threadIdx.x;
    int chunk = (n + 1023) / 1024;
    int start = tid * chunk;
    int end = min(start + chunk, n);
    int s = 0;
    for (int i = start; i < end; i++) s += g_deg[i];
    sums[tid] = s;
    __syncthreads();
    for (int off = 1; off < 1024; off <<= 1) {
        int v = (tid >= off) ? sums[tid - off] : 0;
        __syncthreads();
        sums[tid] += v;
        __syncthreads();
    }
    int base = (tid > 0) ? sums[tid - 1] : 0;
    for (int i = start; i < end; i++) {
        g_rowptr[i] = base;
        g_cursor[i] = base;
        base += g_deg[i];
    }
    if (tid == 1023) g_rowptr[n] = base;
}

__global__ void scatter_kernel(const int* __restrict__ srcE,
                               const int* __restrict__ dstE, int E, int Etot) {
    int i = blockIdx.x * blockDim.x + threadIdx.x;
    if (i < Etot) {
        int s, d;
        if (i < E) { s = srcE[i]; d = dstE[i]; }
        else       { s = d = i - E; }
        int p = atomicAdd(&g_cursor[d], 1);
        g_csrsrc[p] = s;
    }
}

// ---------------- GEMM1: h1 = x @ W1  (M x 256 @ 256 x 256) ----------------
// 128x128x16 tile, 8x8 per thread, 256 threads.
__global__ void __launch_bounds__(256) sgemm1_kernel(const float* __restrict__ A,
                                                     const float* __restrict__ B, int M) {
    const int BM = 128, BN = 128, BK = 16;
    const int K = 256, Ncol = 256;
    const int ASTRIDE = BM + 4; // 132: keeps 16B alignment for float4 reads
    __shared__ float As[BK][ASTRIDE];
    __shared__ float Bs[BK][BN];
    int tid = threadIdx.x;
    int tx = tid & 15;
    int ty = tid >> 4;
    int rowBase = blockIdx.y * BM;
    int colBase = blockIdx.x * BN;

    float acc[8][8];
#pragma unroll
    for (int i = 0; i < 8; i++)
#pragma unroll
        for (int j = 0; j < 8; j++) acc[i][j] = 0.f;

    for (int kk = 0; kk < K; kk += BK) {
#pragma unroll
        for (int l = 0; l < 2; l++) {
            int f = tid + l * 256;
            // A tile: 128 rows x 16 k ; f -> row f/4, k-quad f%4
            int ar = f >> 2, ac = (f & 3) << 2;
            float4 av = make_float4(0.f, 0.f, 0.f, 0.f);
            int grow = rowBase + ar;
            if (grow < M) av = *(const float4*)(A + (size_t)grow * K + kk + ac);
            As[ac + 0][ar] = av.x;
            As[ac + 1][ar] = av.y;
            As[ac + 2][ar] = av.z;
            As[ac + 3][ar] = av.w;
            // B tile: 16 k x 128 cols
            int br = f >> 5, bc = (f & 31) << 2;
            float4 bv = *(const float4*)(B + (size_t)(kk + br) * Ncol + colBase + bc);
            *(float4*)&Bs[br][bc] = bv;
        }
        __syncthreads();
#pragma unroll
        for (int k = 0; k < BK; k++) {
            float a_frag[8], b_frag[8];
            *(float4*)&a_frag[0] = *(const float4*)&As[k][ty * 8];
            *(float4*)&a_frag[4] = *(const float4*)&As[k][ty * 8 + 4];
            *(float4*)&b_frag[0] = *(const float4*)&Bs[k][tx * 8];
            *(float4*)&b_frag[4] = *(const float4*)&Bs[k][tx * 8 + 4];
#pragma unroll
            for (int i = 0; i < 8; i++)
#pragma unroll
                for (int j = 0; j < 8; j++) acc[i][j] += a_frag[i] * b_frag[j];
        }
        __syncthreads();
    }
#pragma unroll
    for (int i = 0; i < 8; i++) {
        int grow = rowBase + ty * 8 + i;
        if (grow >= M) continue;
#pragma unroll
        for (int j = 0; j < 8; j += 4) {
            float4 v = make_float4(acc[i][j], acc[i][j + 1], acc[i][j + 2], acc[i][j + 3]);
            *(float4*)(g_h1 + (size_t)grow * Ncol + colBase + tx * 8 + j) = v;
        }
    }
}

// ---------------- per-node attention logits, layer 1 -----------------------
__global__ void al1_kernel(const float* __restrict__ a_src,
                           const float* __restrict__ a_dst, int N) {
    int i = blockIdx.x * blockDim.x + threadIdx.x;
    if (i >= N * HEADS) return;
    int n = i >> 2, h = i & 3;
    const float4* hp = (const float4*)(g_h1 + (size_t)n * 256 + h * HID);
    const float4* sp = (const float4*)(a_src + h * HID);
    const float4* dp = (const float4*)(a_dst + h * HID);
    float s = 0.f, d = 0.f;
#pragma unroll
    for (int q = 0; q < HID / 4; q++) {
        float4 hv = hp[q], sv = sp[q], dv = dp[q];
        s += hv.x * sv.x + hv.y * sv.y + hv.z * sv.z + hv.w * sv.w;
        d += hv.x * dv.x + hv.y * dv.y + hv.z * dv.z + hv.w * dv.w;
    }
    g_alS1[i] = s;
    g_alD1[i] = d;
}

// ---------------- fused softmax + aggregation, layer 1 ---------------------
// one warp per (node, head); lane covers channels {lane, lane+32}
__global__ void __launch_bounds__(256) agg1_kernel(const float* __restrict__ b1, int N) {
    int gw = blockIdx.x * 8 + (threadIdx.x >> 5);
    int lane = threadIdx.x & 31;
    if (gw >= N * HEADS) return;
    int n = gw >> 2, hh = gw & 3;
    int start = g_rowptr[n], end = g_rowptr[n + 1];
    float ad = g_alD1[n * HEADS + hh];

    // pass 1: segment max over lrelu(alS[src] + alD[dst])
    float m = -INFINITY;
    for (int j = start + lane; j < end; j += 32) {
        int s = g_csrsrc[j];
        float v = g_alS1[s * HEADS + hh] + ad;
        v = (v > 0.f) ? v : 0.2f * v;
        m = fmaxf(m, v);
    }
#pragma unroll
    for (int o = 16; o; o >>= 1) m = fmaxf(m, __shfl_xor_sync(0xffffffffu, m, o));

    // pass 2: exp weights staged in smem (computed once per edge), then
    // all lanes accumulate their 2 channels over the chunk.
    __shared__ float sw_w[8][32];
    __shared__ int   sw_s[8][32];
    int w = threadIdx.x >> 5;
    float acc0 = 0.f, acc1 = 0.f, ssum = 0.f;
    for (int base = start; base < end; base += 32) {
        int cnt = min(32, end - base);
        float wv = 0.f;
        if (lane < cnt) {
            int s = g_csrsrc[base + lane];
            float v = g_alS1[s * HEADS + hh] + ad;
            v = (v > 0.f) ? v : 0.2f * v;
            wv = __expf(v - m);
            sw_w[w][lane] = wv;
            sw_s[w][lane] = s;
        }
        ssum += wv;
        __syncwarp();
        for (int j = 0; j < cnt; j++) {
            float a = sw_w[w][j];
            const float* hp = g_h1 + (size_t)sw_s[w][j] * 256 + hh * HID;
            acc0 += a * hp[lane];
            acc1 += a * hp[lane + 32];
        }
        __syncwarp();
    }
#pragma unroll
    for (int o = 16; o; o >>= 1) ssum += __shfl_xor_sync(0xffffffffu, ssum, o);
    float inv = 1.0f / (ssum + 1e-16f);
    float r0 = acc0 * inv + b1[hh * HID + lane];
    float r1 = acc1 * inv + b1[hh * HID + lane + 32];
    // ELU
    r0 = (r0 > 0.f) ? r0 : expm1f(r0);
    r1 = (r1 > 0.f) ? r1 : expm1f(r1);
    size_t o0 = (size_t)n * 256 + hh * HID;
    g_out1[o0 + lane]      = r0;
    g_out1[o0 + lane + 32] = r1;
}

// ---------------- GEMM2: h2 = out1 @ W2  (M x 256 @ 256 x 40) --------------
// W2 cached fully in smem; 32 rows per block; thread computes 5 outputs.
__global__ void __launch_bounds__(256) gemm2_kernel(const float* __restrict__ W, int M) {
    __shared__ float Ws[256 * OUTC];  // 40 KB
    int tid = threadIdx.x;
    for (int i = tid; i < (256 * OUTC) / 4; i += 256)
        *(float4*)&Ws[i * 4] = *(const float4*)(W + i * 4);
    __syncthreads();

    int r = tid >> 3;          // 0..31  local row
    int g = tid & 7;           // 0..7   col group (5 cols each)
    int grow = blockIdx.x * 32 + r;
    if (grow >= M) return;

    float acc[5] = {0.f, 0.f, 0.f, 0.f, 0.f};
    const float4* ap = (const float4*)(g_out1 + (size_t)grow * 256);
#pragma unroll 4
    for (int k4 = 0; k4 < 64; k4++) {
        float4 a4 = __ldg(&ap[k4]);
        float av[4] = {a4.x, a4.y, a4.z, a4.w};
#pragma unroll
        for (int q = 0; q < 4; q++) {
            const float* wrow = &Ws[(k4 * 4 + q) * OUTC + g * 5];
#pragma unroll
            for (int j = 0; j < 5; j++) acc[j] += av[q] * wrow[j];
        }
    }
#pragma unroll
    for (int j = 0; j < 5; j++) g_h2[(size_t)grow * OUTC + g * 5 + j] = acc[j];
}

// ---------------- per-node attention logits, layer 2 -----------------------
__global__ void al2_kernel(const float* __restrict__ a_src,
                           const float* __restrict__ a_dst, int N) {
    int n = blockIdx.x * blockDim.x + threadIdx.x;
    if (n >= N) return;
    const float4* hp = (const float4*)(g_h2 + (size_t)n * OUTC);
    const float4* sp = (const float4*)a_src;
    const float4* dp = (const float4*)a_dst;
    float s = 0.f, d = 0.f;
#pragma unroll
    for (int q = 0; q < OUTC / 4; q++) {
        float4 hv = hp[q], sv = sp[q], dv = dp[q];
        s += hv.x * sv.x + hv.y * sv.y + hv.z * sv.z + hv.w * sv.w;
        d += hv.x * dv.x + hv.y * dv.y + hv.z * dv.z + hv.w * dv.w;
    }
    g_alS2[n] = s;
    g_alD2[n] = d;
}

// ---------------- fused softmax + aggregation, layer 2 ---------------------
// one warp per node; lane covers channels {lane} and (lane<8) {lane+32}
__global__ void __launch_bounds__(256) agg2_kernel(const float* __restrict__ b2,
                                                   float* __restrict__ out, int N) {
    int n = blockIdx.x * 8 + (threadIdx.x >> 5);
    int lane = threadIdx.x & 31;
    if (n >= N) return;
    int start = g_rowptr[n], end = g_rowptr[n + 1];
    float ad = g_alD2[n];

    float m = -INFINITY;
    for (int j = start + lane; j < end; j += 32) {
        int s = g_csrsrc[j];
        float v = g_alS2[s] + ad;
        v = (v > 0.f) ? v : 0.2f * v;
        m = fmaxf(m, v);
    }
#pragma unroll
    for (int o = 16; o; o >>= 1) m = fmaxf(m, __shfl_xor_sync(0xffffffffu, m, o));

    __shared__ float sw_w[8][32];
    __shared__ int   sw_s[8][32];
    int w = threadIdx.x >> 5;
    float acc0 = 0.f, acc1 = 0.f, ssum = 0.f;
    for (int base = start; base < end; base += 32) {
        int cnt = min(32, end - base);
        float wv = 0.f;
        if (lane < cnt) {
            int s = g_csrsrc[base + lane];
            float v = g_alS2[s] + ad;
            v = (v > 0.f) ? v : 0.2f * v;
            wv = __expf(v - m);
            sw_w[w][lane] = wv;
            sw_s[w][lane] = s;
        }
        ssum += wv;
        __syncwarp();
        for (int j = 0; j < cnt; j++) {
            float a = sw_w[w][j];
            const float* hp = g_h2 + (size_t)sw_s[w][j] * OUTC;
            acc0 += a * hp[lane];
            if (lane < OUTC - 32) acc1 += a * hp[lane + 32];
        }
        __syncwarp();
    }
#pragma unroll
    for (int o = 16; o; o >>= 1) ssum += __shfl_xor_sync(0xffffffffu, ssum, o);
    float inv = 1.0f / (ssum + 1e-16f);
    out[(size_t)n * OUTC + lane] = acc0 * inv + b2[lane];
    if (lane < OUTC - 32)
        out[(size_t)n * OUTC + lane + 32] = acc1 * inv + b2[lane + 32];
}

// ---------------- launch ----------------------------------------------------
extern "C" void kernel_launch(void* const* d_in, const int* in_sizes, int n_in,
                              void* d_out, int out_size) {
    const float* x      = (const float*)d_in[0];
    const int*   ei     = (const int*)d_in[1];
    const float* W1     = (const float*)d_in[2];
    const float* a_src1 = (const float*)d_in[3];
    const float* a_dst1 = (const float*)d_in[4];
    const float* b1     = (const float*)d_in[5];
    const float* W2     = (const float*)d_in[6];
    const float* a_src2 = (const float*)d_in[7];
    const float* a_dst2 = (const float*)d_in[8];
    const float* b2     = (const float*)d_in[9];
    float* out = (float*)d_out;

    int N = in_sizes[0] / 256;   // 50000
    int E = in_sizes[1] / 2;     // 800000
    int Etot = E + N;
    const int* srcE = ei;
    const int* dstE = ei + E;

    // CSR build (by destination, self-loops appended)
    zero_deg_kernel<<<(N + 255) / 256, 256>>>(N);
    deg_kernel<<<(Etot + 255) / 256, 256>>>(dstE, E, Etot);
    scan_kernel<<<1, 1024>>>(N);
    scatter_kernel<<<(Etot + 255) / 256, 256>>>(srcE, dstE, E, Etot);

    // layer 1
    sgemm1_kernel<<<dim3(2, (N + 127) / 128), 256>>>(x, W1, N);
    al1_kernel<<<(N * HEADS + 255) / 256, 256>>>(a_src1, a_dst1, N);
    agg1_kernel<<<(N * HEADS + 7) / 8, 256>>>(b1, N);

    // layer 2
    gemm2_kernel<<<(N + 31) / 32, 256>>>(W2, N);
    al2_kernel<<<(N + 255) / 256, 256>>>(a_src2, a_dst2, N);
    agg2_kernel<<<(N + 7) / 8, 256>>>(b2, out, N);
}